// round 17
// baseline (speedup 1.0000x reference)
#include <cuda_runtime.h>
#include <math.h>

#define FS    39      // total fields
#define NF    38      // fields in pairwise term (0..37)
#define NP    703     // NF*(NF-1)/2 pairs
#define FEAT  100000
#define EMB   10
#define ROWB  (EMB*4) // 40 bytes per row
#define TPB   256
#define KMAX  14      // ceil(703*5 / 256)
#define NPPAD 720     // padded slot table (max slot touched = 716)
#define W     19      // field-block width (2 groups of 19)
#define EPC   3       // elements per CTA
#define BATCH 2048
#define NCTA  ((BATCH + EPC - 1) / EPC)   // 683 -> single wave

// Gather with L1 bypass (.cg): gathered lines have ~0% L1 reuse.
__device__ __forceinline__ float2 ldg_cg(const char* p) {
    float2 r;
    asm("ld.global.cg.v2.f32 {%0, %1}, [%2];"
        : "=f"(r.x), "=f"(r.y) : "l"(p));
    return r;
}

__global__ __launch_bounds__(TPB, 5) void ffm_kernel(
    const int*   __restrict__ idxs,   // [B, FS]
    const float* __restrict__ vals,   // [B, FS]
    const float* __restrict__ emb,    // [FS, FEAT, EMB]
    const float* __restrict__ w1,     // [FEAT]
    float*       __restrict__ out)    // [B]
{
    __shared__ int   s_idx[EPC][FS];
    __shared__ float s_val[EPC][FS];
    __shared__ int4  s_pair[EPC][NPPAD];  // block-sorted descriptors per element
    __shared__ float s_red[EPC][TPB / 32];

    const int t  = threadIdx.x;
    const int b0 = blockIdx.x * EPC;

    // Stage idx/vals for all 3 elements (tail duplicates 2047, write-skipped).
    if (t < EPC * FS) {
        const int e = t / FS;
        const int f = t - e * FS;
        const int bb = min(b0 + e, BATCH - 1);
        s_idx[e][f] = idxs[bb * FS + f];
        s_val[e][f] = vals[bb * FS + f];
    }
    __syncthreads();

    // Zero-scale padding so the main loop needs no bounds guard.
    for (int q = NP + t; q < NPPAD; q += TPB) {
        #pragma unroll
        for (int e = 0; e < EPC; ++e) s_pair[e][q] = make_int4(0, 0, 0, 0);
    }

    // Prologue: decode pair p -> (i, j); scatter descriptors to FIELD-BLOCK-
    // SORTED slots (B0=(lo,lo)[0,171), B1=(lo,hi)[171,532), B2=(hi,hi)[532,703)).
    // Grid is a single wave and all CTAs sweep slots in the same order, so each
    // episode's table working set (<=71MB unique) stays L2-resident chip-wide.
    for (int p = t; p < NP; p += TPB) {
        int i = (int)((75.0f - sqrtf(5625.0f - 8.0f * (float)p)) * 0.5f);
        if (p < i * (75 - i) / 2) --i;
        else if (p >= (i + 1) * (74 - i) / 2) ++i;
        const int base = i * (75 - i) / 2;
        const int j = p - base + i + 1;

        int slot;
        if (j < W) {                       // B0: both lo
            slot = i * (2 * W - i - 1) / 2 + (j - i - 1);
        } else if (i < W) {                // B1: lo x hi
            slot = 171 + i * W + (j - W);
        } else {                           // B2: both hi
            const int ii = i - W;
            slot = 532 + ii * (2 * W - ii - 1) / 2 + (j - i - 1);
        }

        #pragma unroll
        for (int e = 0; e < EPC; ++e) {
            int4 d;
            d.x = (i * FEAT + s_idx[e][j]) * ROWB;
            d.y = (j * FEAT + s_idx[e][i]) * ROWB;
            d.z = __float_as_int(s_val[e][i] * s_val[e][j]);
            d.w = 0;
            s_pair[e][slot] = d;
        }
    }

    float acc0 = 0.f, acc1 = 0.f, acc2 = 0.f;
    // First-order terms, one field per thread per element.
    if (t < FS)              acc0 = w1[s_idx[0][t]]        * s_val[0][t];
    else if (t < 2 * FS)     acc1 = w1[s_idx[1][t - FS]]   * s_val[1][t - FS];
    else if (t < 3 * FS)     acc2 = w1[s_idx[2][t - 2*FS]] * s_val[2][t - 2*FS];
    __syncthreads();

    // Main loop: one slot sweep, 3 elements per iteration (same episode for
    // all elements chip-wide). Per iter: 3 LDS.128 + 6 LDG.64(cg) + 9 FFMA.
    // Incremental (slot, chunk-byte) stepping: stride 256 = 51*5 + 1.
    const char* __restrict__ embB = (const char*)emb;
    int p  = t / 5;
    int cb = (t - p * 5) * 8;

    #pragma unroll
    for (int k = 0; k < KMAX; ++k) {
        const int4 d0 = s_pair[0][p];
        const int4 d1 = s_pair[1][p];
        const int4 d2 = s_pair[2][p];
        const float2 a0 = ldg_cg(embB + (unsigned)(d0.x + cb));
        const float2 v0 = ldg_cg(embB + (unsigned)(d0.y + cb));
        const float2 a1 = ldg_cg(embB + (unsigned)(d1.x + cb));
        const float2 v1 = ldg_cg(embB + (unsigned)(d1.y + cb));
        const float2 a2 = ldg_cg(embB + (unsigned)(d2.x + cb));
        const float2 v2 = ldg_cg(embB + (unsigned)(d2.y + cb));
        acc0 += __int_as_float(d0.z) * (a0.x * v0.x + a0.y * v0.y);
        acc1 += __int_as_float(d1.z) * (a1.x * v1.x + a1.y * v1.y);
        acc2 += __int_as_float(d2.z) * (a2.x * v2.x + a2.y * v2.y);
        p += 51; cb += 8;
        if (cb >= ROWB) { cb -= ROWB; ++p; }
    }

    // Block reductions (3 accumulators).
    #pragma unroll
    for (int o = 16; o > 0; o >>= 1) {
        acc0 += __shfl_down_sync(0xffffffffu, acc0, o);
        acc1 += __shfl_down_sync(0xffffffffu, acc1, o);
        acc2 += __shfl_down_sync(0xffffffffu, acc2, o);
    }
    if ((t & 31) == 0) {
        s_red[0][t >> 5] = acc0;
        s_red[1][t >> 5] = acc1;
        s_red[2][t >> 5] = acc2;
    }
    __syncthreads();
    if (t < EPC) {
        const int bb = b0 + t;
        if (bb < BATCH) {
            float tot = 0.f;
            #pragma unroll
            for (int w = 0; w < TPB / 32; w++) tot += s_red[t][w];
            out[bb] = 1.f / (1.f + expf(-tot));
        }
    }
}

extern "C" void kernel_launch(void* const* d_in, const int* in_sizes, int n_in,
                              void* d_out, int out_size) {
    const int*   idxs = (const int*)d_in[0];
    const float* vals = (const float*)d_in[1];
    const float* emb  = (const float*)d_in[2];
    const float* w1   = (const float*)d_in[3];
    float* out = (float*)d_out;

    ffm_kernel<<<NCTA, TPB>>>(idxs, vals, emb, w1, out);
}